// round 6
// baseline (speedup 1.0000x reference)
#include <cuda_runtime.h>
#include <cfloat>

#define NSETS  8
#define NPTS   4096
#define DF     16
#define KK     16
#define TPB    512
#define WPB    (TPB / 32)     // 16 warps = 16 queries per CTA
#define TILE   256
#define ROWP   20             // padded candidate row stride (floats): 80B -> conflict-free LDS.128

__device__ __forceinline__ unsigned long long pack2(float lo, float hi) {
    unsigned long long r;
    asm("mov.b64 %0, {%1, %2};" : "=l"(r) : "f"(lo), "f"(hi));
    return r;
}
__device__ __forceinline__ void unpack2(unsigned long long v, float& lo, float& hi) {
    asm("mov.b64 {%0, %1}, %2;" : "=f"(lo), "=f"(hi) : "l"(v));
}
__device__ __forceinline__ void fma2(unsigned long long& d, unsigned long long a, unsigned long long b) {
    asm("fma.rn.f32x2 %0, %1, %2, %0;" : "+l"(d) : "l"(a), "l"(b));
}
__device__ __forceinline__ unsigned long long mul2(unsigned long long a, unsigned long long b) {
    unsigned long long d;
    asm("mul.rn.f32x2 %0, %1, %2;" : "=l"(d) : "l"(a), "l"(b));
    return d;
}
__device__ __forceinline__ unsigned long long add2(unsigned long long a, unsigned long long b) {
    unsigned long long d;
    asm("add.rn.f32x2 %0, %1, %2;" : "=l"(d) : "l"(a), "l"(b));
    return d;
}

__global__ __launch_bounds__(TPB, 2)
void knn_warp(const float* __restrict__ x, float* __restrict__ out,
              long long out_elems) {
    __shared__ float sc[TILE * ROWP];   // padded candidate rows
    __shared__ float sch[TILE];         // -0.5 * ||c||^2

    const int tid  = threadIdx.x;
    const int lane = tid & 31;
    const int wid  = tid >> 5;
    const int qrow = blockIdx.x * WPB + wid;        // global query id (set*NPTS+row)
    const int set  = qrow / NPTS;
    const float* __restrict__ xs = x + (size_t)set * NPTS * DF;
    const int row  = qrow - set * NPTS;

    // query row (same for all lanes of the warp), packed into 8 f32x2 lanes
    const float4* qp = reinterpret_cast<const float4*>(xs + (size_t)row * DF);
    float4 q0 = qp[0], q1 = qp[1], q2v = qp[2], q3 = qp[3];
    unsigned long long qq[8];
    qq[0] = pack2(q0.x, q0.y);   qq[1] = pack2(q0.z, q0.w);
    qq[2] = pack2(q1.x, q1.y);   qq[3] = pack2(q1.z, q1.w);
    qq[4] = pack2(q2v.x, q2v.y); qq[5] = pack2(q2v.z, q2v.w);
    qq[6] = pack2(q3.x, q3.y);   qq[7] = pack2(q3.z, q3.w);
    float qn = q0.x*q0.x + q0.y*q0.y + q0.z*q0.z + q0.w*q0.w
             + q1.x*q1.x + q1.y*q1.y + q1.z*q1.z + q1.w*q1.w
             + q2v.x*q2v.x + q2v.y*q2v.y + q2v.z*q2v.z + q2v.w*q2v.w
             + q3.x*q3.x + q3.y*q3.y + q3.z*q3.z + q3.w*q3.w;
    const float qh = -0.5f * qn;

    // warp-distributed top-16: element p lives on lane p (lanes 0..15), sorted ascending
    float list_d = FLT_MAX;
    int   list_i = 0;
    float thr = FLT_MAX;   // current 16th-best (lane 15's value), warp-uniform
    const unsigned FULL = 0xFFFFFFFFu;

    for (int j0 = 0; j0 < NPTS; j0 += TILE) {
        __syncthreads();
        // stage tile: threads 0..TILE-1 each handle one candidate row
        if (tid < TILE) {
            const float4* src = reinterpret_cast<const float4*>(xs + (size_t)(j0 + tid) * DF);
            float4 c0 = src[0], c1 = src[1], c2 = src[2], c3 = src[3];
            float* dst = sc + tid * ROWP;
            *reinterpret_cast<float4*>(dst)      = c0;
            *reinterpret_cast<float4*>(dst + 4)  = c1;
            *reinterpret_cast<float4*>(dst + 8)  = c2;
            *reinterpret_cast<float4*>(dst + 12) = c3;
            float n = c0.x*c0.x + c0.y*c0.y + c0.z*c0.z + c0.w*c0.w
                    + c1.x*c1.x + c1.y*c1.y + c1.z*c1.z + c1.w*c1.w
                    + c2.x*c2.x + c2.y*c2.y + c2.z*c2.z + c2.w*c2.w
                    + c3.x*c3.x + c3.y*c3.y + c3.z*c3.z + c3.w*c3.w;
            sch[tid] = -0.5f * n;
        }
        __syncthreads();

#pragma unroll
        for (int sub = 0; sub < TILE / 32; ++sub) {
            const int c = sub * 32 + lane;           // this lane's candidate (local)
            const ulonglong2* cp = reinterpret_cast<const ulonglong2*>(sc + c * ROWP);
            ulonglong2 v0 = cp[0], v1 = cp[1], v2 = cp[2], v3 = cp[3];

            unsigned long long aA = pack2(qh, sch[c]);
            unsigned long long aB = mul2(qq[1], v0.y);
            fma2(aA, qq[0], v0.x);
            fma2(aB, qq[3], v1.y);
            fma2(aA, qq[2], v1.x);
            fma2(aB, qq[5], v2.y);
            fma2(aA, qq[4], v2.x);
            fma2(aB, qq[7], v3.y);
            fma2(aA, qq[6], v3.x);
            unsigned long long sv = add2(aA, aB);
            float lo, hi;
            unpack2(sv, lo, hi);
            float d = -2.0f * (lo + hi);   // = qn + cn - 2*dot

            unsigned ball = __ballot_sync(FULL, d < thr);
            while (ball) {
                const int b = __ffs(ball) - 1;       // lowest lane = lowest index: tie order OK
                ball &= ball - 1;
                const float dv = __shfl_sync(FULL, d, b);
                const int   iv = j0 + sub * 32 + b;

                // collective insert into distributed sorted list (lanes 0..15)
                float pv = __shfl_up_sync(FULL, list_d, 1);
                int   pi = __shfl_up_sync(FULL, list_i, 1);
                bool  gt  = (list_d > dv);           // strict: equal keeps earlier index
                bool  pgt = (lane != 0) && (pv > dv);
                list_d = gt ? (pgt ? pv : dv) : list_d;
                list_i = gt ? (pgt ? pi : iv) : list_i;
                thr = __shfl_sync(FULL, list_d, KK - 1);
                // prune candidates no longer beating the updated threshold
                ball &= __ballot_sync(FULL, d < thr);
            }
        }
    }

    // write final output directly (no merge kernel)
    const long long E    = (long long)NSETS * NPTS * KK;
    const long long base = (long long)qrow * KK;
    if (lane < KK) {
        if (out_elems >= 3 * E) {
            out[base + lane]         = (float)qrow;
            out[E + base + lane]     = (float)(set * NPTS + list_i);
            out[2 * E + base + lane] = list_d;
        } else {
            out[base + lane] = list_d;
        }
    }
}

extern "C" void kernel_launch(void* const* d_in, const int* in_sizes, int n_in,
                              void* d_out, int out_size) {
    const float* x = (const float*)d_in[0];
    float* out = (float*)d_out;
    knn_warp<<<(NSETS * NPTS) / WPB, TPB>>>(x, out, (long long)out_size);
}

// round 7
// speedup vs baseline: 1.2755x; 1.2755x over previous
#include <cuda_runtime.h>
#include <cfloat>

#define NSETS  8
#define NPTS   4096
#define DF     16
#define KK     16
#define TPB    256
#define WPB    (TPB / 32)       // 8 warps -> 16 queries per CTA
#define QPC    (2 * WPB)        // 16 queries per CTA
#define TILE   256
#define ROWP   20               // padded row stride: conflict-free LDS.128

__device__ __forceinline__ unsigned long long pack2(float lo, float hi) {
    unsigned long long r;
    asm("mov.b64 %0, {%1, %2};" : "=l"(r) : "f"(lo), "f"(hi));
    return r;
}
__device__ __forceinline__ void unpack2(unsigned long long v, float& lo, float& hi) {
    asm("mov.b64 {%0, %1}, %2;" : "=f"(lo), "=f"(hi) : "l"(v));
}
__device__ __forceinline__ void fma2(unsigned long long& d, unsigned long long a, unsigned long long b) {
    asm("fma.rn.f32x2 %0, %1, %2, %0;" : "+l"(d) : "l"(a), "l"(b));
}
__device__ __forceinline__ unsigned long long mul2(unsigned long long a, unsigned long long b) {
    unsigned long long d;
    asm("mul.rn.f32x2 %0, %1, %2;" : "=l"(d) : "l"(a), "l"(b));
    return d;
}
__device__ __forceinline__ unsigned long long add2(unsigned long long a, unsigned long long b) {
    unsigned long long d;
    asm("add.rn.f32x2 %0, %1, %2;" : "=l"(d) : "l"(a), "l"(b));
    return d;
}

__device__ __forceinline__ void load_query(const float* __restrict__ xs, int row,
                                           unsigned long long (&qq)[8], float& qh) {
    const float4* qp = reinterpret_cast<const float4*>(xs + (size_t)row * DF);
    float4 q0 = qp[0], q1 = qp[1], q2 = qp[2], q3 = qp[3];
    qq[0] = pack2(q0.x, q0.y); qq[1] = pack2(q0.z, q0.w);
    qq[2] = pack2(q1.x, q1.y); qq[3] = pack2(q1.z, q1.w);
    qq[4] = pack2(q2.x, q2.y); qq[5] = pack2(q2.z, q2.w);
    qq[6] = pack2(q3.x, q3.y); qq[7] = pack2(q3.z, q3.w);
    float qn = q0.x*q0.x + q0.y*q0.y + q0.z*q0.z + q0.w*q0.w
             + q1.x*q1.x + q1.y*q1.y + q1.z*q1.z + q1.w*q1.w
             + q2.x*q2.x + q2.y*q2.y + q2.z*q2.z + q2.w*q2.w
             + q3.x*q3.x + q3.y*q3.y + q3.z*q3.z + q3.w*q3.w;
    qh = -0.5f * qn;
}

__global__ __launch_bounds__(TPB, 2)
void knn_warp2(const float* __restrict__ x, float* __restrict__ out,
               long long out_elems) {
    __shared__ float sc[TILE * ROWP];
    __shared__ float sch[TILE];

    const int tid  = threadIdx.x;
    const int lane = tid & 31;
    const int wid  = tid >> 5;
    const unsigned FULL = 0xFFFFFFFFu;

    const int qbase = blockIdx.x * QPC;          // 16 consecutive queries, same set
    const int qrowA = qbase + 2 * wid;
    const int qrowB = qrowA + 1;
    const int set   = qrowA / NPTS;
    const int rowA  = qrowA - set * NPTS;
    const int rowB  = rowA + 1;
    const float* __restrict__ xs = x + (size_t)set * NPTS * DF;

    unsigned long long qqA[8], qqB[8];
    float qhA, qhB;
    load_query(xs, rowA, qqA, qhA);
    load_query(xs, rowB, qqB, qhB);

    // distributed top-16 lists: lanes 0..15 = list A (ascending), lanes 16..31 = list B
    float list_d = FLT_MAX;
    int   list_i = 0;
    float thrA = FLT_MAX, thrB = FLT_MAX;
    const bool inA   = (lane < KK);
    const bool headA = (lane == 0);
    const bool headB = (lane == KK);

    for (int j0 = 0; j0 < NPTS; j0 += TILE) {
        __syncthreads();
        // stage tile: one candidate row per thread
        {
            const float4* src = reinterpret_cast<const float4*>(xs + (size_t)(j0 + tid) * DF);
            float4 c0 = src[0], c1 = src[1], c2 = src[2], c3 = src[3];
            float* dst = sc + tid * ROWP;
            *reinterpret_cast<float4*>(dst)      = c0;
            *reinterpret_cast<float4*>(dst + 4)  = c1;
            *reinterpret_cast<float4*>(dst + 8)  = c2;
            *reinterpret_cast<float4*>(dst + 12) = c3;
            float n = c0.x*c0.x + c0.y*c0.y + c0.z*c0.z + c0.w*c0.w
                    + c1.x*c1.x + c1.y*c1.y + c1.z*c1.z + c1.w*c1.w
                    + c2.x*c2.x + c2.y*c2.y + c2.z*c2.z + c2.w*c2.w
                    + c3.x*c3.x + c3.y*c3.y + c3.z*c3.z + c3.w*c3.w;
            sch[tid] = -0.5f * n;
        }
        __syncthreads();

#pragma unroll
        for (int sub = 0; sub < TILE / 32; ++sub) {
            const int c = sub * 32 + lane;        // this lane's candidate (local in tile)
            const ulonglong2* cp = reinterpret_cast<const ulonglong2*>(sc + c * ROWP);
            ulonglong2 v0 = cp[0], v1 = cp[1], v2 = cp[2], v3 = cp[3];
            const float ch = sch[c];

            // two independent FMA chain pairs (A and B)
            unsigned long long aA0 = pack2(qhA, ch);
            unsigned long long aA1 = mul2(qqA[1], v0.y);
            unsigned long long aB0 = pack2(qhB, ch);
            unsigned long long aB1 = mul2(qqB[1], v0.y);
            fma2(aA0, qqA[0], v0.x);  fma2(aB0, qqB[0], v0.x);
            fma2(aA1, qqA[3], v1.y);  fma2(aB1, qqB[3], v1.y);
            fma2(aA0, qqA[2], v1.x);  fma2(aB0, qqB[2], v1.x);
            fma2(aA1, qqA[5], v2.y);  fma2(aB1, qqB[5], v2.y);
            fma2(aA0, qqA[4], v2.x);  fma2(aB0, qqB[4], v2.x);
            fma2(aA1, qqA[7], v3.y);  fma2(aB1, qqB[7], v3.y);
            fma2(aA0, qqA[6], v3.x);  fma2(aB0, qqB[6], v3.x);

            unsigned long long sA = add2(aA0, aA1);
            unsigned long long sB = add2(aB0, aB1);
            float alo, ahi, blo, bhi;
            unpack2(sA, alo, ahi);
            unpack2(sB, blo, bhi);
            float dA = -2.0f * (alo + ahi);       // = ||q-c||^2
            float dB = -2.0f * (blo + bhi);

            const int idx0 = j0 + sub * 32;

            // ---- list A hits (lanes 0..15 hold list) ----
            unsigned ballA = __ballot_sync(FULL, dA < thrA);
            while (ballA) {
                const int b = __ffs(ballA) - 1;   // ascending lane = ascending index
                ballA &= ballA - 1;
                const float dv = __shfl_sync(FULL, dA, b);
                const int   iv = idx0 + b;
                float pv = __shfl_up_sync(FULL, list_d, 1);
                int   pi = __shfl_up_sync(FULL, list_i, 1);
                bool gt  = (list_d > dv);
                bool pgt = (!headA) && (pv > dv);
                if (inA) {
                    if (gt) { list_d = pgt ? pv : dv; list_i = pgt ? pi : iv; }
                }
                thrA = __shfl_sync(FULL, list_d, KK - 1);
                ballA &= __ballot_sync(FULL, dA < thrA);
            }

            // ---- list B hits (lanes 16..31 hold list) ----
            unsigned ballB = __ballot_sync(FULL, dB < thrB);
            while (ballB) {
                const int b = __ffs(ballB) - 1;
                ballB &= ballB - 1;
                const float dv = __shfl_sync(FULL, dB, b);
                const int   iv = idx0 + b;
                float pv = __shfl_up_sync(FULL, list_d, 1);
                int   pi = __shfl_up_sync(FULL, list_i, 1);
                bool gt  = (list_d > dv);
                bool pgt = (!headB) && (pv > dv);
                if (!inA) {
                    if (gt) { list_d = pgt ? pv : dv; list_i = pgt ? pi : iv; }
                }
                thrB = __shfl_sync(FULL, list_d, 31);
                ballB &= __ballot_sync(FULL, dB < thrB);
            }
        }
    }

    // write outputs directly
    const long long E = (long long)NSETS * NPTS * KK;
    if (out_elems >= 3 * E) {
        if (inA) {
            const long long base = (long long)qrowA * KK + lane;
            out[base]         = (float)qrowA;
            out[E + base]     = (float)(set * NPTS + list_i);
            out[2 * E + base] = list_d;
        } else {
            const long long base = (long long)qrowB * KK + (lane - KK);
            out[base]         = (float)qrowB;
            out[E + base]     = (float)(set * NPTS + list_i);
            out[2 * E + base] = list_d;
        }
    } else {
        if (inA) out[(long long)qrowA * KK + lane] = list_d;
        else     out[(long long)qrowB * KK + (lane - KK)] = list_d;
    }
}

extern "C" void kernel_launch(void* const* d_in, const int* in_sizes, int n_in,
                              void* d_out, int out_size) {
    const float* x = (const float*)d_in[0];
    float* out = (float*)d_out;
    knn_warp2<<<(NSETS * NPTS) / QPC, TPB>>>(x, out, (long long)out_size);
}

// round 9
// speedup vs baseline: 1.2792x; 1.0029x over previous
#include <cuda_runtime.h>
#include <cfloat>

#define NSETS  8
#define NPTS   4096
#define DF     16
#define KK     16
#define TPB    256
#define WPB    (TPB / 32)       // 8 warps
#define QPW    4                // queries per warp
#define QPC    (WPB * QPW)      // 32 queries per CTA
#define TILE   256
#define ROWP   20               // padded row stride: conflict-free LDS.128

__device__ __forceinline__ unsigned long long pack2(float lo, float hi) {
    unsigned long long r;
    asm("mov.b64 %0, {%1, %2};" : "=l"(r) : "f"(lo), "f"(hi));
    return r;
}
__device__ __forceinline__ void unpack2(unsigned long long v, float& lo, float& hi) {
    asm("mov.b64 {%0, %1}, %2;" : "=f"(lo), "=f"(hi) : "l"(v));
}
__device__ __forceinline__ void fma2(unsigned long long& d, unsigned long long a, unsigned long long b) {
    asm("fma.rn.f32x2 %0, %1, %2, %0;" : "+l"(d) : "l"(a), "l"(b));
}
__device__ __forceinline__ unsigned long long mul2(unsigned long long a, unsigned long long b) {
    unsigned long long d;
    asm("mul.rn.f32x2 %0, %1, %2;" : "=l"(d) : "l"(a), "l"(b));
    return d;
}
__device__ __forceinline__ unsigned long long add2(unsigned long long a, unsigned long long b) {
    unsigned long long d;
    asm("add.rn.f32x2 %0, %1, %2;" : "=l"(d) : "l"(a), "l"(b));
    return d;
}

__device__ __forceinline__ void load_query(const float* __restrict__ xs, int row,
                                           unsigned long long (&qq)[8], float& qh) {
    const float4* qp = reinterpret_cast<const float4*>(xs + (size_t)row * DF);
    float4 q0 = qp[0], q1 = qp[1], q2 = qp[2], q3 = qp[3];
    qq[0] = pack2(q0.x, q0.y); qq[1] = pack2(q0.z, q0.w);
    qq[2] = pack2(q1.x, q1.y); qq[3] = pack2(q1.z, q1.w);
    qq[4] = pack2(q2.x, q2.y); qq[5] = pack2(q2.z, q2.w);
    qq[6] = pack2(q3.x, q3.y); qq[7] = pack2(q3.z, q3.w);
    float qn = q0.x*q0.x + q0.y*q0.y + q0.z*q0.z + q0.w*q0.w
             + q1.x*q1.x + q1.y*q1.y + q1.z*q1.z + q1.w*q1.w
             + q2.x*q2.x + q2.y*q2.y + q2.z*q2.z + q2.w*q2.w
             + q3.x*q3.x + q3.y*q3.y + q3.z*q3.z + q3.w*q3.w;
    qh = -0.5f * qn;
}

// distance of one candidate (v0..v3, ch) to one query (qq, qh)
__device__ __forceinline__ float dist_one(const unsigned long long (&qq)[8], float qh,
                                          ulonglong2 v0, ulonglong2 v1,
                                          ulonglong2 v2, ulonglong2 v3, float ch) {
    unsigned long long a0 = pack2(qh, ch);
    unsigned long long a1 = mul2(qq[1], v0.y);
    fma2(a0, qq[0], v0.x);
    fma2(a1, qq[3], v1.y);
    fma2(a0, qq[2], v1.x);
    fma2(a1, qq[5], v2.y);
    fma2(a0, qq[4], v2.x);
    fma2(a1, qq[7], v3.y);
    fma2(a0, qq[6], v3.x);
    unsigned long long s = add2(a0, a1);
    float lo, hi;
    unpack2(s, lo, hi);
    return -2.0f * (lo + hi);   // = ||q-c||^2
}

// collective insert into a distributed sorted list (half-warp holds 16 elems)
// in_grp: this lane belongs to the list's half; head_lane: first lane of half.
__device__ __forceinline__ void insert_dist(float& list_d, int& list_i,
                                            float dv, int iv,
                                            bool in_grp, bool is_head) {
    const unsigned FULL = 0xFFFFFFFFu;
    float pv = __shfl_up_sync(FULL, list_d, 1);
    int   pi = __shfl_up_sync(FULL, list_i, 1);
    bool gt  = (list_d > dv);
    bool pgt = (!is_head) && (pv > dv);
    if (in_grp && gt) {
        list_d = pgt ? pv : dv;
        list_i = pgt ? pi : iv;
    }
}

__global__ __launch_bounds__(TPB, 2)
void knn_warp4(const float* __restrict__ x, float* __restrict__ out,
               long long out_elems) {
    __shared__ float sc[TILE * ROWP];
    __shared__ float sch[TILE];

    const int tid  = threadIdx.x;
    const int lane = tid & 31;
    const int wid  = tid >> 5;
    const unsigned FULL = 0xFFFFFFFFu;

    const int qbase = blockIdx.x * QPC;          // 32 consecutive queries, same set
    const int q0r   = qbase + QPW * wid;         // this warp's 4 queries
    const int set   = q0r / NPTS;
    const int row0  = q0r - set * NPTS;
    const float* __restrict__ xs = x + (size_t)set * NPTS * DF;

    unsigned long long qqA[8], qqB[8], qqC[8], qqD[8];
    float qhA, qhB, qhC, qhD;
    load_query(xs, row0 + 0, qqA, qhA);
    load_query(xs, row0 + 1, qqB, qhB);
    load_query(xs, row0 + 2, qqC, qhC);
    load_query(xs, row0 + 3, qqD, qhD);

    // layer1: lanes 0-15 = list A, lanes 16-31 = list B
    // layer2: lanes 0-15 = list C, lanes 16-31 = list D
    float l1_d = FLT_MAX, l2_d = FLT_MAX;
    int   l1_i = 0,       l2_i = 0;
    float thrA = FLT_MAX, thrB = FLT_MAX, thrC = FLT_MAX, thrD = FLT_MAX;
    const bool loHalf = (lane < KK);
    const bool headLo = (lane == 0);
    const bool headHi = (lane == KK);

    for (int j0 = 0; j0 < NPTS; j0 += TILE) {
        __syncthreads();
        {
            const float4* src = reinterpret_cast<const float4*>(xs + (size_t)(j0 + tid) * DF);
            float4 c0 = src[0], c1 = src[1], c2 = src[2], c3 = src[3];
            float* dst = sc + tid * ROWP;
            *reinterpret_cast<float4*>(dst)      = c0;
            *reinterpret_cast<float4*>(dst + 4)  = c1;
            *reinterpret_cast<float4*>(dst + 8)  = c2;
            *reinterpret_cast<float4*>(dst + 12) = c3;
            float n = c0.x*c0.x + c0.y*c0.y + c0.z*c0.z + c0.w*c0.w
                    + c1.x*c1.x + c1.y*c1.y + c1.z*c1.z + c1.w*c1.w
                    + c2.x*c2.x + c2.y*c2.y + c2.z*c2.z + c2.w*c2.w
                    + c3.x*c3.x + c3.y*c3.y + c3.z*c3.z + c3.w*c3.w;
            sch[tid] = -0.5f * n;
        }
        __syncthreads();

#pragma unroll
        for (int sub = 0; sub < TILE / 32; ++sub) {
            const int c = sub * 32 + lane;
            const ulonglong2* cp = reinterpret_cast<const ulonglong2*>(sc + c * ROWP);
            ulonglong2 v0 = cp[0], v1 = cp[1], v2 = cp[2], v3 = cp[3];
            const float ch = sch[c];

            float dA = dist_one(qqA, qhA, v0, v1, v2, v3, ch);
            float dB = dist_one(qqB, qhB, v0, v1, v2, v3, ch);
            float dC = dist_one(qqC, qhC, v0, v1, v2, v3, ch);
            float dD = dist_one(qqD, qhD, v0, v1, v2, v3, ch);

            const int idx0 = j0 + sub * 32;

            unsigned ball = __ballot_sync(FULL, dA < thrA);
            while (ball) {
                const int b = __ffs(ball) - 1;
                ball &= ball - 1;
                insert_dist(l1_d, l1_i, __shfl_sync(FULL, dA, b), idx0 + b, loHalf, headLo);
                thrA = __shfl_sync(FULL, l1_d, KK - 1);
                ball &= __ballot_sync(FULL, dA < thrA);
            }
            ball = __ballot_sync(FULL, dB < thrB);
            while (ball) {
                const int b = __ffs(ball) - 1;
                ball &= ball - 1;
                insert_dist(l1_d, l1_i, __shfl_sync(FULL, dB, b), idx0 + b, !loHalf, headHi);
                thrB = __shfl_sync(FULL, l1_d, 31);
                ball &= __ballot_sync(FULL, dB < thrB);
            }
            ball = __ballot_sync(FULL, dC < thrC);
            while (ball) {
                const int b = __ffs(ball) - 1;
                ball &= ball - 1;
                insert_dist(l2_d, l2_i, __shfl_sync(FULL, dC, b), idx0 + b, loHalf, headLo);
                thrC = __shfl_sync(FULL, l2_d, KK - 1);
                ball &= __ballot_sync(FULL, dC < thrC);
            }
            ball = __ballot_sync(FULL, dD < thrD);
            while (ball) {
                const int b = __ffs(ball) - 1;
                ball &= ball - 1;
                insert_dist(l2_d, l2_i, __shfl_sync(FULL, dD, b), idx0 + b, !loHalf, headHi);
                thrD = __shfl_sync(FULL, l2_d, 31);
                ball &= __ballot_sync(FULL, dD < thrD);
            }
        }
    }

    // write outputs directly
    const long long E = (long long)NSETS * NPTS * KK;
    const int p    = loHalf ? lane : (lane - KK);
    const int qr1  = loHalf ? (q0r + 0) : (q0r + 1);   // layer1 query
    const int qr2  = loHalf ? (q0r + 2) : (q0r + 3);   // layer2 query
    if (out_elems >= 3 * E) {
        long long b1 = (long long)qr1 * KK + p;
        out[b1]         = (float)qr1;
        out[E + b1]     = (float)(set * NPTS + l1_i);
        out[2 * E + b1] = l1_d;
        long long b2 = (long long)qr2 * KK + p;
        out[b2]         = (float)qr2;
        out[E + b2]     = (float)(set * NPTS + l2_i);
        out[2 * E + b2] = l2_d;
    } else {
        out[(long long)qr1 * KK + p] = l1_d;
        out[(long long)qr2 * KK + p] = l2_d;
    }
}

extern "C" void kernel_launch(void* const* d_in, const int* in_sizes, int n_in,
                              void* d_out, int out_size) {
    const float* x = (const float*)d_in[0];
    float* out = (float*)d_out;
    knn_warp4<<<(NSETS * NPTS) / QPC, TPB>>>(x, out, (long long)out_size);
}

// round 10
// speedup vs baseline: 1.5587x; 1.2185x over previous
#include <cuda_runtime.h>
#include <cfloat>

#define NSETS  8
#define NPTS   4096
#define DF     16
#define KK     16
#define TPB    256
#define WPB    (TPB / 32)       // 8 warps
#define QPW    4                // queries per warp
#define QPC    (WPB * QPW)      // 32 queries per CTA
#define TILE   256
#define ROWP   20               // padded row stride: conflict-free LDS.128

__device__ __forceinline__ unsigned long long pack2(float lo, float hi) {
    unsigned long long r;
    asm("mov.b64 %0, {%1, %2};" : "=l"(r) : "f"(lo), "f"(hi));
    return r;
}
__device__ __forceinline__ void unpack2(unsigned long long v, float& lo, float& hi) {
    asm("mov.b64 {%0, %1}, %2;" : "=f"(lo), "=f"(hi) : "l"(v));
}
__device__ __forceinline__ void fma2(unsigned long long& d, unsigned long long a, unsigned long long b) {
    asm("fma.rn.f32x2 %0, %1, %2, %0;" : "+l"(d) : "l"(a), "l"(b));
}
__device__ __forceinline__ unsigned long long mul2(unsigned long long a, unsigned long long b) {
    unsigned long long d;
    asm("mul.rn.f32x2 %0, %1, %2;" : "=l"(d) : "l"(a), "l"(b));
    return d;
}
__device__ __forceinline__ unsigned long long add2(unsigned long long a, unsigned long long b) {
    unsigned long long d;
    asm("add.rn.f32x2 %0, %1, %2;" : "=l"(d) : "l"(a), "l"(b));
    return d;
}

__device__ __forceinline__ void load_query(const float* __restrict__ xs, int row,
                                           unsigned long long (&qq)[8], float& qh) {
    const float4* qp = reinterpret_cast<const float4*>(xs + (size_t)row * DF);
    float4 q0 = qp[0], q1 = qp[1], q2 = qp[2], q3 = qp[3];
    qq[0] = pack2(q0.x, q0.y); qq[1] = pack2(q0.z, q0.w);
    qq[2] = pack2(q1.x, q1.y); qq[3] = pack2(q1.z, q1.w);
    qq[4] = pack2(q2.x, q2.y); qq[5] = pack2(q2.z, q2.w);
    qq[6] = pack2(q3.x, q3.y); qq[7] = pack2(q3.z, q3.w);
    float qn = q0.x*q0.x + q0.y*q0.y + q0.z*q0.z + q0.w*q0.w
             + q1.x*q1.x + q1.y*q1.y + q1.z*q1.z + q1.w*q1.w
             + q2.x*q2.x + q2.y*q2.y + q2.z*q2.z + q2.w*q2.w
             + q3.x*q3.x + q3.y*q3.y + q3.z*q3.z + q3.w*q3.w;
    qh = -0.5f * qn;
}

__device__ __forceinline__ float dist_one(const unsigned long long (&qq)[8], float qh,
                                          ulonglong2 v0, ulonglong2 v1,
                                          ulonglong2 v2, ulonglong2 v3, float ch) {
    unsigned long long a0 = pack2(qh, ch);
    unsigned long long a1 = mul2(qq[1], v0.y);
    fma2(a0, qq[0], v0.x);
    fma2(a1, qq[3], v1.y);
    fma2(a0, qq[2], v1.x);
    fma2(a1, qq[5], v2.y);
    fma2(a0, qq[4], v2.x);
    fma2(a1, qq[7], v3.y);
    fma2(a0, qq[6], v3.x);
    unsigned long long s = add2(a0, a1);
    float lo, hi;
    unpack2(s, lo, hi);
    return -2.0f * (lo + hi);   // = ||q-c||^2
}

// paired drain: lanes 0..15 hold list for dLo's query, lanes 16..31 for dHi's.
// Processes one hit from each half per iteration; lazy threshold refresh at end.
__device__ __forceinline__ void drain_pair(float& list_d, int& list_i,
                                           float dLo, float dHi,
                                           float& thrLo, float& thrHi,
                                           int idx0, bool loHalf, int lane) {
    const unsigned FULL = 0xFFFFFFFFu;
    unsigned ballA = __ballot_sync(FULL, dLo < thrLo);
    unsigned ballB = __ballot_sync(FULL, dHi < thrHi);
    if (ballA | ballB) {
        while (ballA | ballB) {
            const bool hasA = (ballA != 0), hasB = (ballB != 0);
            const int bA = hasA ? (__ffs(ballA) - 1) : 0;
            const int bB = hasB ? (__ffs(ballB) - 1) : 0;
            ballA &= ballA - 1;
            ballB &= ballB - 1;
            const float dvA = __shfl_sync(FULL, dLo, bA);
            const float dvB = __shfl_sync(FULL, dHi, bB);
            const float dv = loHalf ? dvA : dvB;
            const int   iv = idx0 + (loHalf ? bA : bB);
            const bool valid = loHalf ? hasA : hasB;
            const float pv = __shfl_up_sync(FULL, list_d, 1);
            const int   pi = __shfl_up_sync(FULL, list_i, 1);
            const bool gt  = (list_d > dv);
            const bool pgt = (lane != 0 && lane != KK) && (pv > dv);
            if (valid && gt) {
                list_d = pgt ? pv : dv;
                list_i = pgt ? pi : iv;
            }
        }
        thrLo = __shfl_sync(FULL, list_d, KK - 1);
        thrHi = __shfl_sync(FULL, list_d, 31);
    }
}

__global__ __launch_bounds__(TPB, 2)
void knn_warp4(const float* __restrict__ x, float* __restrict__ out,
               long long out_elems) {
    __shared__ float sc[TILE * ROWP];
    __shared__ float sch[TILE];

    const int tid  = threadIdx.x;
    const int lane = tid & 31;
    const int wid  = tid >> 5;

    const int qbase = blockIdx.x * QPC;
    const int q0r   = qbase + QPW * wid;
    const int set   = q0r / NPTS;
    const int row0  = q0r - set * NPTS;
    const float* __restrict__ xs = x + (size_t)set * NPTS * DF;

    unsigned long long qqA[8], qqB[8], qqC[8], qqD[8];
    float qhA, qhB, qhC, qhD;
    load_query(xs, row0 + 0, qqA, qhA);
    load_query(xs, row0 + 1, qqB, qhB);
    load_query(xs, row0 + 2, qqC, qhC);
    load_query(xs, row0 + 3, qqD, qhD);

    // layer1: lanes 0-15 = list A, lanes 16-31 = list B
    // layer2: lanes 0-15 = list C, lanes 16-31 = list D
    float l1_d = FLT_MAX, l2_d = FLT_MAX;
    int   l1_i = 0,       l2_i = 0;
    float thrA = FLT_MAX, thrB = FLT_MAX, thrC = FLT_MAX, thrD = FLT_MAX;
    const bool loHalf = (lane < KK);

    for (int j0 = 0; j0 < NPTS; j0 += TILE) {
        __syncthreads();
        {
            const float4* src = reinterpret_cast<const float4*>(xs + (size_t)(j0 + tid) * DF);
            float4 c0 = src[0], c1 = src[1], c2 = src[2], c3 = src[3];
            float* dst = sc + tid * ROWP;
            *reinterpret_cast<float4*>(dst)      = c0;
            *reinterpret_cast<float4*>(dst + 4)  = c1;
            *reinterpret_cast<float4*>(dst + 8)  = c2;
            *reinterpret_cast<float4*>(dst + 12) = c3;
            float n = c0.x*c0.x + c0.y*c0.y + c0.z*c0.z + c0.w*c0.w
                    + c1.x*c1.x + c1.y*c1.y + c1.z*c1.z + c1.w*c1.w
                    + c2.x*c2.x + c2.y*c2.y + c2.z*c2.z + c2.w*c2.w
                    + c3.x*c3.x + c3.y*c3.y + c3.z*c3.z + c3.w*c3.w;
            sch[tid] = -0.5f * n;
        }
        __syncthreads();

#pragma unroll
        for (int sub = 0; sub < TILE / 32; ++sub) {
            const int c = sub * 32 + lane;
            const ulonglong2* cp = reinterpret_cast<const ulonglong2*>(sc + c * ROWP);
            ulonglong2 v0 = cp[0], v1 = cp[1], v2 = cp[2], v3 = cp[3];
            const float ch = sch[c];

            float dA = dist_one(qqA, qhA, v0, v1, v2, v3, ch);
            float dB = dist_one(qqB, qhB, v0, v1, v2, v3, ch);
            float dC = dist_one(qqC, qhC, v0, v1, v2, v3, ch);
            float dD = dist_one(qqD, qhD, v0, v1, v2, v3, ch);

            const int idx0 = j0 + sub * 32;
            drain_pair(l1_d, l1_i, dA, dB, thrA, thrB, idx0, loHalf, lane);
            drain_pair(l2_d, l2_i, dC, dD, thrC, thrD, idx0, loHalf, lane);
        }
    }

    // write outputs directly
    const long long E = (long long)NSETS * NPTS * KK;
    const int p    = loHalf ? lane : (lane - KK);
    const int qr1  = loHalf ? (q0r + 0) : (q0r + 1);
    const int qr2  = loHalf ? (q0r + 2) : (q0r + 3);
    if (out_elems >= 3 * E) {
        long long b1 = (long long)qr1 * KK + p;
        out[b1]         = (float)qr1;
        out[E + b1]     = (float)(set * NPTS + l1_i);
        out[2 * E + b1] = l1_d;
        long long b2 = (long long)qr2 * KK + p;
        out[b2]         = (float)qr2;
        out[E + b2]     = (float)(set * NPTS + l2_i);
        out[2 * E + b2] = l2_d;
    } else {
        out[(long long)qr1 * KK + p] = l1_d;
        out[(long long)qr2 * KK + p] = l2_d;
    }
}

extern "C" void kernel_launch(void* const* d_in, const int* in_sizes, int n_in,
                              void* d_out, int out_size) {
    const float* x = (const float*)d_in[0];
    float* out = (float*)d_out;
    knn_warp4<<<(NSETS * NPTS) / QPC, TPB>>>(x, out, (long long)out_size);
}